// round 3
// baseline (speedup 1.0000x reference)
#include <cuda_runtime.h>
#include <cstdint>

// ---------------------------------------------------------------------------
// CropConvNeuralProcess: stride-2 3x3 conv, B=32, Cin=Cout=256, 64x64 -> 32x32.
// Crop mask is provably all-ones -> pure convolution.
//
// Implicit GEMM on legacy tensor cores (mma.sync m16n8k8 tf32 — base-target
// PTX; tcgen05 is unavailable because the harness compiles via compute_103
// virtual arch which rejects all 'a'-suffix features).
//
//   D[cout, sp] = sum_k W_t[cout,k'] * Xcol[sp,k'],  k' = (kh*3+kw)*256+cin
//   CTA tile: M=128 (cout), N=128 (4 output rows x 32 cols), K chunks of 32.
//   Grid = 32 images x 8 sp-tiles x 2 cout-tiles = 512 CTAs, 256 threads.
// ---------------------------------------------------------------------------

__device__ uint32_t g_Wt[256 * 2304];   // W as [cout][tap][cin], tf32-rounded bits

static constexpr int A_PITCH = 36;                  // floats; bank = 4*row+col (conflict-free frags)
static constexpr int B_PITCH = 136;                 // floats; bank = 8*k+n   (conflict-free frags)
static constexpr int A_FLOATS = 128 * A_PITCH;      // 4608
static constexpr int B_FLOATS = 32 * B_PITCH;       // 4352
static constexpr int B_BASE   = 2 * A_FLOATS;       // 9216
static constexpr int SMEM_BYTES = (2 * A_FLOATS + 2 * B_FLOATS) * 4;  // 71680

// --------------------------- helpers ---------------------------------------

__device__ __forceinline__ uint32_t smem_u32(const void* p) {
    uint32_t a;
    asm("{ .reg .u64 t; cvta.to.shared.u64 t, %1; cvt.u32.u64 %0, t; }" : "=r"(a) : "l"(p));
    return a;
}

__device__ __forceinline__ uint32_t tf32r(float f) {
    uint32_t r;
    asm("cvt.rna.tf32.f32 %0, %1;" : "=r"(r) : "f"(f));
    return r;
}

__device__ __forceinline__ void cp_async16(uint32_t dst, const void* src) {
    asm volatile("cp.async.ca.shared.global [%0], [%1], 16;" :: "r"(dst), "l"(src));
}

__device__ __forceinline__ void mma_tf32(float* c, uint32_t a0, uint32_t a1,
                                         uint32_t a2, uint32_t a3,
                                         uint32_t b0, uint32_t b1) {
    asm volatile(
        "mma.sync.aligned.m16n8k8.row.col.f32.tf32.tf32.f32 "
        "{%0,%1,%2,%3}, {%4,%5,%6,%7}, {%8,%9}, {%0,%1,%2,%3};"
        : "+f"(c[0]), "+f"(c[1]), "+f"(c[2]), "+f"(c[3])
        : "r"(a0), "r"(a1), "r"(a2), "r"(a3), "r"(b0), "r"(b1));
}

// --------------------------- prep kernel -----------------------------------
// W[cout][cin][3][3] f32 -> g_Wt[cout][tap][cin] tf32 bits (round-to-nearest)
__global__ void __launch_bounds__(256) prep_kernel(const float* __restrict__ w) {
    int i = blockIdx.x * 256 + threadIdx.x;     // i = cout*256 + cin
    int cout = i >> 8;
    int cin  = i & 255;
    const float* src = w + (size_t)i * 9;
    uint32_t* dst = g_Wt + (size_t)cout * 2304 + cin;
#pragma unroll
    for (int t = 0; t < 9; t++)
        dst[t * 256] = tf32r(src[t]);
}

// --------------------------- main kernel -----------------------------------

__global__ void __launch_bounds__(256, 2) conv_kernel(const float* __restrict__ x,
                                                      float* __restrict__ out) {
    extern __shared__ float smf[];
    uint32_t* smu = reinterpret_cast<uint32_t*>(smf);
    const uint32_t smem_base = smem_u32(smf);

    const int tid  = threadIdx.x;
    const int lane = tid & 31;
    const int wid  = tid >> 5;
    const int warp_m = wid >> 2;        // 0..1
    const int warp_n = wid & 3;         // 0..3

    const int bid = blockIdx.x;         // 512 CTAs
    const int ct  = bid & 1;
    const int spt = (bid >> 1) & 7;
    const int b   = bid >> 4;
    const int cout0 = ct * 128;
    const int oh0   = spt * 4;
    const int sp0   = spt * 128;

    const float* xb = x + (size_t)b * 256 * 4096;

    float acc[4][4][4];
#pragma unroll
    for (int i = 0; i < 4; i++)
#pragma unroll
        for (int j = 0; j < 4; j++)
#pragma unroll
            for (int k = 0; k < 4; k++) acc[i][j][k] = 0.f;

    float4 v[8];

    // ---- im2col gather: fill v[8] for chunk c ----
    auto gather = [&](int c) {
        const int tap = c >> 3, cb = c & 7;
        const int kh  = tap / 3;
        const int c0  = cb * 32;
#pragma unroll
        for (int g = 0; g < 8; g++) {
            int gi = tid + (g << 8);
            int j  = gi & 15;            // float4 position along iw
            int r  = (gi >> 4) & 3;      // output row in tile
            int cc = gi >> 6;            // cin within 32-block
            int ih = 2 * (oh0 + r) + kh - 1;
            if (ih >= 0)
                v[g] = *reinterpret_cast<const float4*>(
                    xb + (((size_t)(c0 + cc)) << 12) + (ih << 6) + (j << 2));
            else
                v[g] = make_float4(0.f, 0.f, 0.f, 0.f);
        }
    };

    // ---- convert + store B tile [k=32][n=128] at float-offset boff ----
    auto stsB = [&](int c, int boff) {
        const int tap = c >> 3;
        const int kw  = tap - (tap / 3) * 3;
#pragma unroll
        for (int g = 0; g < 8; g++) {
            int gi = tid + (g << 8);
            int j  = gi & 15;
            int r  = (gi >> 4) & 3;
            int k  = gi >> 6;
            int n0 = r * 32;
            int base = boff + k * B_PITCH + n0;
            float4 q = v[g];
            if (kw == 1) {               // iw = 2*ow: x -> ow=2j, z -> ow=2j+1
                *reinterpret_cast<uint2*>(&smu[base + 2 * j]) =
                    make_uint2(tf32r(q.x), tf32r(q.z));
            } else if (kw == 2) {        // iw = 2*ow+1: y -> 2j, w -> 2j+1
                *reinterpret_cast<uint2*>(&smu[base + 2 * j]) =
                    make_uint2(tf32r(q.y), tf32r(q.w));
            } else {                     // kw==0: iw = 2*ow-1: y -> 2j+1, w -> 2j+2
                smu[base + 2 * j + 1] = tf32r(q.y);
                if (j < 15) smu[base + 2 * j + 2] = tf32r(q.w);
                if (j == 0) smu[base] = 0u;          // ow=0 hits iw=-1 padding
            }
        }
    };

    // ---- cp.async A tile [m=128][k=32] at float-offset aoff ----
    auto cpA = [&](int c, int aoff) {
#pragma unroll
        for (int i = 0; i < 4; i++) {
            int idx = tid + (i << 8);            // 1024 x 16B
            int row = idx >> 3, c4 = idx & 7;
            const void* src = &g_Wt[(size_t)(cout0 + row) * 2304 + c * 32 + c4 * 4];
            uint32_t dst = smem_base + (uint32_t)(aoff + row * A_PITCH + c4 * 4) * 4u;
            cp_async16(dst, src);
        }
    };

    // ---- MMA over one 32-K chunk ----
    auto domma = [&](int aoff, int boff) {
        const int arow = lane >> 2;      // 0..7
        const int acol = lane & 3;       // 0..3
        const int abase = aoff + (warp_m * 64 + arow) * A_PITCH + acol;
        const int bbase = boff + acol * B_PITCH + warp_n * 32 + arow;
#pragma unroll
        for (int kc = 0; kc < 4; kc++) {
            uint32_t bf[4][2];
#pragma unroll
            for (int nt = 0; nt < 4; nt++) {
                bf[nt][0] = smu[bbase + kc * 8 * B_PITCH + nt * 8];
                bf[nt][1] = smu[bbase + (kc * 8 + 4) * B_PITCH + nt * 8];
            }
#pragma unroll
            for (int mt = 0; mt < 4; mt++) {
                uint32_t a0 = smu[abase + (mt * 16) * A_PITCH + kc * 8];
                uint32_t a1 = smu[abase + (mt * 16 + 8) * A_PITCH + kc * 8];
                uint32_t a2 = smu[abase + (mt * 16) * A_PITCH + kc * 8 + 4];
                uint32_t a3 = smu[abase + (mt * 16 + 8) * A_PITCH + kc * 8 + 4];
#pragma unroll
                for (int nt = 0; nt < 4; nt++)
                    mma_tf32(acc[mt][nt], a0, a1, a2, a3, bf[nt][0], bf[nt][1]);
            }
        }
    };

    // chunk order: kh outer, cin-block mid, kw inner (L1 reuse of input rows)
    auto chunk_of = [](int it) {
        int kh = it / 24, rem = it - kh * 24;
        int cb = rem / 3, kw = rem - cb * 3;
        return (kh * 3 + kw) * 8 + cb;
    };

    // ---- prologue: chunk 0 ----
    {
        int c0h = chunk_of(0);
        gather(c0h);
        cpA(c0h, 0);
        asm volatile("cp.async.commit_group;" ::: "memory");
        stsB(c0h, B_BASE);
    }

    // ---- main loop ----
    for (int it = 0; it < 72; it++) {
        const int buf  = it & 1;
        const int aoff = buf ? A_FLOATS : 0;
        const int boff = B_BASE + (buf ? B_FLOATS : 0);
        const int naoff = buf ? 0 : A_FLOATS;
        const int nboff = B_BASE + (buf ? 0 : B_FLOATS);
        const bool more = (it + 1 < 72);
        const int cn = more ? chunk_of(it + 1) : 0;

        if (more) gather(cn);                        // LDGs fly during MMA below
        asm volatile("cp.async.wait_group 0;" ::: "memory");
        __syncthreads();                             // A(it), B(it) visible to all
        if (more) {
            cpA(cn, naoff);
            asm volatile("cp.async.commit_group;" ::: "memory");
        }
        domma(aoff, boff);
        if (more) stsB(cn, nboff);
    }

    // ---- epilogue: direct coalesced STG.64 ----
    const size_t outbase = ((size_t)(b * 256 + cout0)) * 1024 + sp0;
#pragma unroll
    for (int mt = 0; mt < 4; mt++) {
#pragma unroll
        for (int nt = 0; nt < 4; nt++) {
            int m = warp_m * 64 + mt * 16 + (lane >> 2);
            int n = warp_n * 32 + nt * 8 + 2 * (lane & 3);
            *reinterpret_cast<float2*>(&out[outbase + (size_t)m * 1024 + n]) =
                make_float2(acc[mt][nt][0], acc[mt][nt][1]);
            *reinterpret_cast<float2*>(&out[outbase + (size_t)(m + 8) * 1024 + n]) =
                make_float2(acc[mt][nt][2], acc[mt][nt][3]);
        }
    }
}

// --------------------------- launch ----------------------------------------
extern "C" void kernel_launch(void* const* d_in, const int* in_sizes, int n_in,
                              void* d_out, int out_size) {
    const float* x = (const float*)d_in[0];
    const float* w = (const float*)d_in[1];
    float* out = (float*)d_out;
    (void)in_sizes; (void)n_in; (void)out_size;

    prep_kernel<<<256, 256>>>(w);

    cudaFuncSetAttribute(conv_kernel, cudaFuncAttributeMaxDynamicSharedMemorySize, SMEM_BYTES);
    conv_kernel<<<512, 256, SMEM_BYTES>>>(x, out);
}